// round 11
// baseline (speedup 1.0000x reference)
#include <cuda_runtime.h>
#include <cuda_fp16.h>
#include <cuda_bf16.h>
#include <cstdint>

#define NUM_USERS 100000
#define NUM_ITEMS 100000
#define N_NODES   200000
#define EMB       64
#define N_EDGES   3200000

#define SCAN_TILE 1024
#define SCAN_BLOCKS ((N_NODES + 1 + SCAN_TILE - 1) / SCAN_TILE)   // 196

// ---------------- device scratch (allocation-free rule: static globals) ----
__device__ __half g_h0[(size_t)N_NODES * EMB];    // 25.6 MB  (x0, then y2)
__device__ __half g_h1[(size_t)N_NODES * EMB];    // 25.6 MB  (y1)
__device__ int    g_cnt[N_NODES];
__device__ int    g_rowptr[N_NODES + 1];
__device__ int    g_cursor[N_NODES];
__device__ int2   g_edges[N_EDGES];               // (col, w-bits) interleaved
__device__ int    g_bsum [SCAN_BLOCKS + 8];
__device__ int    g_bsum2[SCAN_BLOCKS + 8];

// ---------------- helpers --------------------------------------------------
__device__ __forceinline__ unsigned pack_half2(__half2 h) {
    return ((unsigned)__half_as_ushort(__high2half(h)) << 16) |
           (unsigned)__half_as_ushort(__low2half(h));
}

__device__ __forceinline__ float2 unpack_h2(unsigned u) {
    __half2 h;
    *(unsigned*)&h = u;
    return __half22float2(h);
}

__device__ __forceinline__ int block_excl_scan_1024(int v) {
    __shared__ int warp_sums[32];
    const int lane = threadIdx.x & 31;
    const int wid  = threadIdx.x >> 5;
    int incl = v;
    #pragma unroll
    for (int o = 1; o < 32; o <<= 1) {
        int n = __shfl_up_sync(0xFFFFFFFFu, incl, o);
        if (lane >= o) incl += n;
    }
    if (lane == 31) warp_sums[wid] = incl;
    __syncthreads();
    if (wid == 0) {
        int ws = warp_sums[lane];
        #pragma unroll
        for (int o = 1; o < 32; o <<= 1) {
            int n = __shfl_up_sync(0xFFFFFFFFu, ws, o);
            if (lane >= o) ws += n;
        }
        warp_sums[lane] = ws;
    }
    __syncthreads();
    int warp_off = (wid > 0) ? warp_sums[wid - 1] : 0;
    return warp_off + incl - v;
}

// ---------------- ego init: concat + fp32->fp16 into g_h0; zero g_cnt ------
__global__ void k_convert(const float4* __restrict__ u,
                          const float4* __restrict__ it) {
    const int half_f4  = NUM_USERS * EMB / 4;
    const int total_f4 = N_NODES * EMB / 4;
    int i = blockIdx.x * blockDim.x + threadIdx.x;
    if (i < N_NODES) g_cnt[i] = 0;          // fused zero of histogram
    if (i >= total_f4) return;
    float4 v = (i < half_f4) ? u[i] : it[i - half_f4];
    uint2 packed;
    packed.x = pack_half2(__floats2half2_rn(v.x, v.y));
    packed.y = pack_half2(__floats2half2_rn(v.z, v.w));
    ((uint2*)g_h0)[i] = packed;
}

// ---------------- CSR build -------------------------------------------------
__global__ void k_hist(const int* __restrict__ erow) {
    int e = blockIdx.x * blockDim.x + threadIdx.x;
    if (e < N_EDGES) atomicAdd(&g_cnt[erow[e]], 1);
}

__global__ void k_scan_blocksums() {
    int i = blockIdx.x * SCAN_TILE + threadIdx.x;
    int v = (i < N_NODES) ? g_cnt[i] : 0;
    __shared__ int sh[32];
    #pragma unroll
    for (int o = 16; o; o >>= 1) v += __shfl_down_sync(0xFFFFFFFFu, v, o);
    if ((threadIdx.x & 31) == 0) sh[threadIdx.x >> 5] = v;
    __syncthreads();
    if (threadIdx.x < 32) {
        int t = sh[threadIdx.x];
        #pragma unroll
        for (int o = 16; o; o >>= 1) t += __shfl_down_sync(0xFFFFFFFFu, t, o);
        if (threadIdx.x == 0) g_bsum[blockIdx.x] = t;
    }
}

__global__ void k_scan_sums() {
    int v = (threadIdx.x < SCAN_BLOCKS) ? g_bsum[threadIdx.x] : 0;
    int ex = block_excl_scan_1024(v);
    if (threadIdx.x < SCAN_BLOCKS) g_bsum2[threadIdx.x] = ex;
}

__global__ void k_scan_final() {
    int i = blockIdx.x * SCAN_TILE + threadIdx.x;
    int v = (i < N_NODES) ? g_cnt[i] : 0;
    int ex = block_excl_scan_1024(v) + g_bsum2[blockIdx.x];
    if (i < N_NODES) {
        g_rowptr[i] = ex;
        g_cursor[i] = ex;
    } else if (i == N_NODES) {
        g_rowptr[N_NODES] = ex;
    }
}

__global__ void k_scatter(const int* __restrict__ erow,
                          const int* __restrict__ ecol,
                          const float* __restrict__ ew) {
    int e = blockIdx.x * blockDim.x + threadIdx.x;
    if (e < N_EDGES) {
        int r = erow[e];
        int p = atomicAdd(&g_cursor[r], 1);
        g_edges[p] = make_int2(ecol[e], __float_as_int(ew[e]));
    }
}

// ---------------- SpMM: one warp per row, 8 lanes per edge -----------------
// Each lane loads uint4 = 8 fp16 embs (16B); 8 lanes cover one 128B row.
// The warp processes 4 edges per iteration (quarter-warps 0..3), with a
// depth-2 software pipeline on the gather (MLP=2 per warp).
// LAYER 1: gather h0 -> write y1 to h1
// LAYER 2: gather h1 -> write y2 to h0
// LAYER 3: gather h0 -> out = (h1[row] + h0[row] + y3) / 3
template <int LAYER>
__global__ void __launch_bounds__(256) k_spmm(float* __restrict__ out) {
    const int gw = (blockIdx.x * blockDim.x + threadIdx.x) >> 5;
    if (gw >= N_NODES) return;
    const int lane = threadIdx.x & 31;
    const int q  = lane >> 3;   // which edge of the quad
    const int ql = lane & 7;    // emb-chunk index (8 embs per lane)

    const uint4* __restrict__ x8 =
        (const uint4*)((LAYER == 2) ? g_h1 : g_h0);

    const int s = __ldg(&g_rowptr[gw]);
    const int e = __ldg(&g_rowptr[gw + 1]);

    float a0 = 0.f, a1 = 0.f, a2 = 0.f, a3 = 0.f;
    float a4 = 0.f, a5 = 0.f, a6 = 0.f, a7 = 0.f;

    for (int base = s; base < e; base += 32) {
        int cnt = e - base; if (cnt > 32) cnt = 32;
        int2 ed = (lane < cnt) ? __ldg(&g_edges[base + lane]) : make_int2(0, 0);
        const int iters = (cnt + 3) >> 2;

        // prologue: prefetch t = 0
        int   c0 = __shfl_sync(0xFFFFFFFFu, ed.x, q);
        int   b0 = __shfl_sync(0xFFFFFFFFu, ed.y, q);
        float w  = (q < cnt) ? __int_as_float(b0) : 0.0f;
        uint4 v  = __ldg(&x8[c0 * 8 + ql]);

        for (int t = 0; t < iters; t++) {
            uint4 vn = make_uint4(0u, 0u, 0u, 0u);
            float wn = 0.0f;
            if (t + 1 < iters) {                 // warp-uniform branch
                int ns  = 4 * (t + 1) + q;
                int nc  = __shfl_sync(0xFFFFFFFFu, ed.x, ns);
                int nwb = __shfl_sync(0xFFFFFFFFu, ed.y, ns);
                wn = (ns < cnt) ? __int_as_float(nwb) : 0.0f;
                vn = __ldg(&x8[nc * 8 + ql]);    // in flight during FMAs below
            }
            float2 p0 = unpack_h2(v.x);
            float2 p1 = unpack_h2(v.y);
            float2 p2 = unpack_h2(v.z);
            float2 p3 = unpack_h2(v.w);
            a0 = fmaf(w, p0.x, a0);  a1 = fmaf(w, p0.y, a1);
            a2 = fmaf(w, p1.x, a2);  a3 = fmaf(w, p1.y, a3);
            a4 = fmaf(w, p2.x, a4);  a5 = fmaf(w, p2.y, a5);
            a6 = fmaf(w, p3.x, a6);  a7 = fmaf(w, p3.y, a7);
            v = vn; w = wn;
        }
    }

    // reduce the 4 quarter-warp partials (lanes L, L^8, L^16, L^24)
    a0 += __shfl_xor_sync(0xFFFFFFFFu, a0, 8);
    a1 += __shfl_xor_sync(0xFFFFFFFFu, a1, 8);
    a2 += __shfl_xor_sync(0xFFFFFFFFu, a2, 8);
    a3 += __shfl_xor_sync(0xFFFFFFFFu, a3, 8);
    a4 += __shfl_xor_sync(0xFFFFFFFFu, a4, 8);
    a5 += __shfl_xor_sync(0xFFFFFFFFu, a5, 8);
    a6 += __shfl_xor_sync(0xFFFFFFFFu, a6, 8);
    a7 += __shfl_xor_sync(0xFFFFFFFFu, a7, 8);
    a0 += __shfl_xor_sync(0xFFFFFFFFu, a0, 16);
    a1 += __shfl_xor_sync(0xFFFFFFFFu, a1, 16);
    a2 += __shfl_xor_sync(0xFFFFFFFFu, a2, 16);
    a3 += __shfl_xor_sync(0xFFFFFFFFu, a3, 16);
    a4 += __shfl_xor_sync(0xFFFFFFFFu, a4, 16);
    a5 += __shfl_xor_sync(0xFFFFFFFFu, a5, 16);
    a6 += __shfl_xor_sync(0xFFFFFFFFu, a6, 16);
    a7 += __shfl_xor_sync(0xFFFFFFFFu, a7, 16);

    if (lane < 8) {
        if (LAYER < 3) {
            uint4 st;
            st.x = pack_half2(__floats2half2_rn(a0, a1));
            st.y = pack_half2(__floats2half2_rn(a2, a3));
            st.z = pack_half2(__floats2half2_rn(a4, a5));
            st.w = pack_half2(__floats2half2_rn(a6, a7));
            ((uint4*)((LAYER == 1) ? g_h1 : g_h0))[gw * 8 + ql] = st;
        } else {
            uint4 v1 = ((const uint4*)g_h1)[gw * 8 + ql];   // y1 (own row)
            uint4 v2 = ((const uint4*)g_h0)[gw * 8 + ql];   // y2 (own row)
            float2 u0 = unpack_h2(v1.x), u1 = unpack_h2(v1.y);
            float2 u2 = unpack_h2(v1.z), u3 = unpack_h2(v1.w);
            float2 t0 = unpack_h2(v2.x), t1 = unpack_h2(v2.y);
            float2 t2 = unpack_h2(v2.z), t3 = unpack_h2(v2.w);
            const float inv3 = 1.0f / 3.0f;
            float4 r0, r1;
            r0.x = (u0.x + t0.x + a0) * inv3;
            r0.y = (u0.y + t0.y + a1) * inv3;
            r0.z = (u1.x + t1.x + a2) * inv3;
            r0.w = (u1.y + t1.y + a3) * inv3;
            r1.x = (u2.x + t2.x + a4) * inv3;
            r1.y = (u2.y + t2.y + a5) * inv3;
            r1.z = (u3.x + t3.x + a6) * inv3;
            r1.w = (u3.y + t3.y + a7) * inv3;
            float4* o4 = (float4*)out;
            __stcs(&o4[gw * 16 + ql * 2],     r0);
            __stcs(&o4[gw * 16 + ql * 2 + 1], r1);
        }
    }
}

// ---------------- launch ----------------------------------------------------
extern "C" void kernel_launch(void* const* d_in, const int* in_sizes, int n_in,
                              void* d_out, int out_size) {
    (void)in_sizes; (void)n_in; (void)out_size;
    const float* u   = (const float*)d_in[0];
    const float* it  = (const float*)d_in[1];
    const float* ew  = (const float*)d_in[2];
    const int*   er  = (const int*)d_in[3];
    const int*   ec  = (const int*)d_in[4];
    float*       out = (float*)d_out;

    // ego init (concat + fp16 convert) fused with histogram zeroing
    k_convert<<<(N_NODES * EMB / 4 + 255) / 256, 256>>>((const float4*)u,
                                                        (const float4*)it);
    // CSR build
    k_hist<<<(N_EDGES + 255) / 256, 256>>>(er);
    k_scan_blocksums<<<SCAN_BLOCKS, SCAN_TILE>>>();
    k_scan_sums<<<1, SCAN_TILE>>>();
    k_scan_final<<<SCAN_BLOCKS, SCAN_TILE>>>();
    k_scatter<<<(N_EDGES + 255) / 256, 256>>>(er, ec, ew);

    // 3 propagation layers (one warp per row)
    const int spmm_blocks = (N_NODES * 32 + 255) / 256;
    k_spmm<1><<<spmm_blocks, 256>>>(out);
    k_spmm<2><<<spmm_blocks, 256>>>(out);
    k_spmm<3><<<spmm_blocks, 256>>>(out);
}